// round 3
// baseline (speedup 1.0000x reference)
#include <cuda_runtime.h>
#include <stdint.h>

#define NUM_BINS 256
#define NCH_SAMPLE 3
#define NCH_TOTAL 6
#define NPX (2048 * 4096)

// Static device scratch (zero-initialized at module load; each run restores
// the zeroed invariant itself, so graph replays are deterministic).
__device__ int           g_hist[NCH_SAMPLE][NUM_BINS];
__device__ float         g_lut[NCH_SAMPLE][NUM_BINS];
__device__ int           g_ticket;
__device__ unsigned char g_bins[(size_t)NCH_SAMPLE * NPX];   // 25 MB bin cache

// K1: read sample channels once (streaming), write uint8 bins, build smem
// histograms, flush with global atomics. Last block computes all 3 LUTs and
// resets g_hist / g_ticket.
__global__ void hist_bin_lut_kernel(const float* __restrict__ img, int npx) {
    __shared__ int sh[4][NUM_BINS];
    __shared__ int s_flag;
    const int c = blockIdx.y;
    const int t = threadIdx.x;

    for (int i = t; i < 4 * NUM_BINS; i += blockDim.x) ((int*)sh)[i] = 0;
    __syncthreads();

    const float4* p = (const float4*)(img + (size_t)c * npx);
    uchar4*       b = (uchar4*)(g_bins + (size_t)c * npx);
    const int n4 = npx >> 2;
    const int sub = t & 3;
    const int stride = gridDim.x * blockDim.x;

    for (int i = blockIdx.x * blockDim.x + t; i < n4; i += stride) {
        float4 v = __ldcs(&p[i]);            // evict-first: don't pollute L2
        int bx = min(NUM_BINS - 1, max(0, (int)v.x));
        int by = min(NUM_BINS - 1, max(0, (int)v.y));
        int bz = min(NUM_BINS - 1, max(0, (int)v.z));
        int bw = min(NUM_BINS - 1, max(0, (int)v.w));
        b[i] = make_uchar4((unsigned char)bx, (unsigned char)by,
                           (unsigned char)bz, (unsigned char)bw);
        atomicAdd(&sh[sub][bx], 1);
        atomicAdd(&sh[sub][by], 1);
        atomicAdd(&sh[sub][bz], 1);
        atomicAdd(&sh[sub][bw], 1);
    }
    __syncthreads();

    for (int i = t; i < NUM_BINS; i += blockDim.x) {
        int s = sh[0][i] + sh[1][i] + sh[2][i] + sh[3][i];
        if (s) atomicAdd(&g_hist[c][i], s);
    }

    // ---- last-block LUT computation (replaces separate lut_kernel) ----
    __threadfence();                          // release hist updates
    if (t == 0) {
        int done = atomicAdd(&g_ticket, 1);
        s_flag = (done == (int)(gridDim.x * gridDim.y) - 1);
    }
    __syncthreads();
    if (!s_flag) return;

    __shared__ int hist[NUM_BINS];
    __shared__ int cum[NUM_BINS];
    __shared__ int s_lastnz;

    for (int ch = 0; ch < NCH_SAMPLE; ch++) {
        // volatile load: bypass any stale L1 copy, see other blocks' atomics
        int h = *(volatile int*)&g_hist[ch][t];
        hist[t] = h;
        cum[t] = h;
        if (t == 0) s_lastnz = 0;
        __syncthreads();

        #pragma unroll
        for (int off = 1; off < NUM_BINS; off <<= 1) {
            int tmp = (t >= off) ? cum[t - off] : 0;
            __syncthreads();
            cum[t] += tmp;
            __syncthreads();
        }
        if (h > 0) atomicMax(&s_lastnz, t);
        __syncthreads();

        const int total = cum[NUM_BINS - 1];
        const int step  = (total - hist[s_lastnz]) / (NUM_BINS - 1);

        float outv;
        if (step == 0) {
            outv = (float)t;                  // identity when step==0
        } else {
            int l = (t == 0) ? 0 : (cum[t - 1] + (step >> 1)) / step;
            outv = (float)min(NUM_BINS - 1, max(0, l));
        }
        g_lut[ch][t] = outv;
        g_hist[ch][t] = 0;                    // reset for next replay
        __syncthreads();
    }
    if (t == 0) g_ticket = 0;
}

// K2: all 6 channels. c<3: read 16 bins/thread from L2-hot cache, write 4
// float4s. c>=3: streaming float4 copy.
__global__ void apply_all_kernel(const float* __restrict__ img,
                                 float* __restrict__ out, int npx) {
    const int c = blockIdx.y;
    const int stride = gridDim.x * blockDim.x;

    if (c < NCH_SAMPLE) {
        __shared__ float lut[NUM_BINS];
        for (int i = threadIdx.x; i < NUM_BINS; i += blockDim.x)
            lut[i] = g_lut[c][i];
        __syncthreads();

        const uint4* b = (const uint4*)(g_bins + (size_t)c * npx);
        float4*      q = (float4*)(out + (size_t)c * npx);
        const int n16 = npx >> 4;

        for (int i = blockIdx.x * blockDim.x + threadIdx.x; i < n16; i += stride) {
            uint4 w = b[i];
            float4 r0, r1, r2, r3;
            r0.x = lut[w.x & 255]; r0.y = lut[(w.x >> 8) & 255];
            r0.z = lut[(w.x >> 16) & 255]; r0.w = lut[w.x >> 24];
            r1.x = lut[w.y & 255]; r1.y = lut[(w.y >> 8) & 255];
            r1.z = lut[(w.y >> 16) & 255]; r1.w = lut[w.y >> 24];
            r2.x = lut[w.z & 255]; r2.y = lut[(w.z >> 8) & 255];
            r2.z = lut[(w.z >> 16) & 255]; r2.w = lut[w.z >> 24];
            r3.x = lut[w.w & 255]; r3.y = lut[(w.w >> 8) & 255];
            r3.z = lut[(w.w >> 16) & 255]; r3.w = lut[w.w >> 24];
            q[i * 4 + 0] = r0;
            q[i * 4 + 1] = r1;
            q[i * 4 + 2] = r2;
            q[i * 4 + 3] = r3;
        }
    } else {
        const float4* p = (const float4*)(img + (size_t)c * npx);
        float4*       q = (float4*)(out + (size_t)c * npx);
        const int n4 = npx >> 2;
        for (int i = blockIdx.x * blockDim.x + threadIdx.x; i < n4; i += stride)
            q[i] = __ldcs(&p[i]);
    }
}

extern "C" void kernel_launch(void* const* d_in, const int* in_sizes, int n_in,
                              void* d_out, int out_size) {
    const float* img = (const float*)d_in[0];
    float* out = (float*)d_out;
    const int npx = in_sizes[0] / NCH_TOTAL;   // 2048*4096

    hist_bin_lut_kernel<<<dim3(296, NCH_SAMPLE), 256>>>(img, npx);
    apply_all_kernel<<<dim3(1024, NCH_TOTAL), 256>>>(img, out, npx);
}

// round 4
// speedup vs baseline: 1.1003x; 1.1003x over previous
#include <cuda_runtime.h>
#include <stdint.h>

#define NUM_BINS 256
#define NCH_SAMPLE 3
#define NCH_TOTAL 6
#define NPX (2048 * 4096)

// Static device scratch. Zero at module load; each run restores the zeroed
// invariant itself (hist + ticket), so graph replays are deterministic.
__device__ int           g_hist[NCH_SAMPLE][NUM_BINS];
__device__ float         g_lut[NCH_SAMPLE][NUM_BINS];
__device__ int           g_ticket;
__device__ unsigned char g_bins[(size_t)NCH_SAMPLE * NPX];   // 25 MB bin cache

// K1: read samples once (streaming hint), write uint8 bins (default policy ->
// stays dirty in L2 for K2), build smem histograms, flush via global atomics.
// Ticket-elected last block computes all 3 LUTs and resets hist/ticket.
__global__ void hist_bin_lut_kernel(const float* __restrict__ img, int npx) {
    __shared__ int sh[4][NUM_BINS];
    __shared__ int s_flag;
    const int c = blockIdx.y;
    const int t = threadIdx.x;

    for (int i = t; i < 4 * NUM_BINS; i += blockDim.x) ((int*)sh)[i] = 0;
    __syncthreads();

    const float4* p = (const float4*)(img + (size_t)c * npx);
    uchar4*       b = (uchar4*)(g_bins + (size_t)c * npx);
    const int n4 = npx >> 2;
    const int sub = t & 3;
    const int stride = gridDim.x * blockDim.x;

    for (int i = blockIdx.x * blockDim.x + t; i < n4; i += stride) {
        float4 v = __ldcs(&p[i]);            // evict-first: protect L2 for bins
        int bx = min(NUM_BINS - 1, max(0, (int)v.x));
        int by = min(NUM_BINS - 1, max(0, (int)v.y));
        int bz = min(NUM_BINS - 1, max(0, (int)v.z));
        int bw = min(NUM_BINS - 1, max(0, (int)v.w));
        b[i] = make_uchar4((unsigned char)bx, (unsigned char)by,
                           (unsigned char)bz, (unsigned char)bw);
        atomicAdd(&sh[sub][bx], 1);
        atomicAdd(&sh[sub][by], 1);
        atomicAdd(&sh[sub][bz], 1);
        atomicAdd(&sh[sub][bw], 1);
    }
    __syncthreads();

    for (int i = t; i < NUM_BINS; i += blockDim.x) {
        int s = sh[0][i] + sh[1][i] + sh[2][i] + sh[3][i];
        if (s) atomicAdd(&g_hist[c][i], s);
    }

    // ---- last arriving block computes the LUTs ----
    __threadfence();
    if (t == 0) {
        int done = atomicAdd(&g_ticket, 1);
        s_flag = (done == (int)(gridDim.x * gridDim.y) - 1);
    }
    __syncthreads();
    if (!s_flag) return;

    __shared__ int hist[NUM_BINS];
    __shared__ int cum[NUM_BINS];
    __shared__ int s_lastnz;

    for (int ch = 0; ch < NCH_SAMPLE; ch++) {
        int h = *(volatile int*)&g_hist[ch][t];
        hist[t] = h;
        cum[t] = h;
        if (t == 0) s_lastnz = 0;
        __syncthreads();

        #pragma unroll
        for (int off = 1; off < NUM_BINS; off <<= 1) {
            int tmp = (t >= off) ? cum[t - off] : 0;
            __syncthreads();
            cum[t] += tmp;
            __syncthreads();
        }
        if (h > 0) atomicMax(&s_lastnz, t);
        __syncthreads();

        const int total = cum[NUM_BINS - 1];
        const int step  = (total - hist[s_lastnz]) / (NUM_BINS - 1);

        float outv;
        if (step == 0) {
            outv = (float)t;                  // identity when step==0
        } else {
            int l = (t == 0) ? 0 : (cum[t - 1] + (step >> 1)) / step;
            outv = (float)min(NUM_BINS - 1, max(0, l));
        }
        g_lut[ch][t] = outv;
        g_hist[ch][t] = 0;                    // reset for next graph replay
        __syncthreads();
    }
    if (t == 0) g_ticket = 0;
}

// K2: all 6 channels in one launch.
//   c < 3 : 1 uchar4 load (coalesced, L2-hot) -> 4 smem LUT gathers ->
//           1 float4 store (coalesced, streaming).
//   c >= 3: float4 streaming copy.
__global__ void apply_all_kernel(const float* __restrict__ img,
                                 float* __restrict__ out, int npx) {
    const int c = blockIdx.y;
    const int stride = gridDim.x * blockDim.x;
    const int n4 = npx >> 2;

    if (c < NCH_SAMPLE) {
        __shared__ float lut[NUM_BINS];
        for (int i = threadIdx.x; i < NUM_BINS; i += blockDim.x)
            lut[i] = g_lut[c][i];
        __syncthreads();

        const uchar4* b = (const uchar4*)(g_bins + (size_t)c * npx);
        float4*       q = (float4*)(out + (size_t)c * npx);

        int i = blockIdx.x * blockDim.x + threadIdx.x;
        for (; i + stride < n4; i += 2 * stride) {
            uchar4 v0 = b[i];
            uchar4 v1 = b[i + stride];
            float4 r0, r1;
            r0.x = lut[v0.x]; r0.y = lut[v0.y]; r0.z = lut[v0.z]; r0.w = lut[v0.w];
            r1.x = lut[v1.x]; r1.y = lut[v1.y]; r1.z = lut[v1.z]; r1.w = lut[v1.w];
            __stcs(&q[i], r0);
            __stcs(&q[i + stride], r1);
        }
        if (i < n4) {
            uchar4 v = b[i];
            float4 r;
            r.x = lut[v.x]; r.y = lut[v.y]; r.z = lut[v.z]; r.w = lut[v.w];
            __stcs(&q[i], r);
        }
    } else {
        const float4* p = (const float4*)(img + (size_t)c * npx);
        float4*       q = (float4*)(out + (size_t)c * npx);
        int i = blockIdx.x * blockDim.x + threadIdx.x;
        for (; i + stride < n4; i += 2 * stride) {
            float4 a = __ldcs(&p[i]);
            float4 d = __ldcs(&p[i + stride]);
            __stcs(&q[i], a);
            __stcs(&q[i + stride], d);
        }
        if (i < n4) __stcs(&q[i], __ldcs(&p[i]));
    }
}

extern "C" void kernel_launch(void* const* d_in, const int* in_sizes, int n_in,
                              void* d_out, int out_size) {
    const float* img = (const float*)d_in[0];
    float* out = (float*)d_out;
    const int npx = in_sizes[0] / NCH_TOTAL;   // 2048*4096

    hist_bin_lut_kernel<<<dim3(296, NCH_SAMPLE), 256>>>(img, npx);
    apply_all_kernel<<<dim3(1024, NCH_TOTAL), 256>>>(img, out, npx);
}

// round 5
// speedup vs baseline: 1.2496x; 1.1356x over previous
#include <cuda_runtime.h>
#include <stdint.h>

#define NUM_BINS 256
#define NCH_SAMPLE 3
#define NCH_TOTAL 6
#define NPX (2048 * 4096)
#define NREP 8   // smem histogram replicas

// Static device scratch. Zeroed at module load; each run restores the zeroed
// invariant (hist + ticket) itself, so graph replays are deterministic.
__device__ int           g_hist[NCH_SAMPLE][NUM_BINS];
__device__ float         g_lut[NCH_SAMPLE][NUM_BINS];
__device__ int           g_ticket;
__device__ unsigned char g_bins[(size_t)NCH_SAMPLE * NPX];   // 25 MB bin cache

// K1: y<3 -> hist+binize samples; y>=3 -> streaming target copy (overlaps the
// atomic-bound hist phase with pure-bandwidth work). Ticket-elected last hist
// block computes all 3 LUTs and resets hist/ticket.
__global__ void __launch_bounds__(256)
hist_copy_kernel(const float* __restrict__ img, float* __restrict__ out,
                 int npx) {
    const int c = blockIdx.y;
    const int t = threadIdx.x;
    const int stride = gridDim.x * blockDim.x;
    const int n4 = npx >> 2;

    if (c >= NCH_SAMPLE) {
        // ---- target channel: streaming float4 copy ----
        const float4* p = (const float4*)(img + (size_t)c * npx);
        float4*       q = (float4*)(out + (size_t)c * npx);
        int i = blockIdx.x * blockDim.x + t;
        for (; i + stride < n4; i += 2 * stride) {
            float4 a = __ldcs(&p[i]);
            float4 d = __ldcs(&p[i + stride]);
            __stcs(&q[i], a);
            __stcs(&q[i + stride], d);
        }
        if (i < n4) __stcs(&q[i], __ldcs(&p[i]));
        return;
    }

    // ---- sample channel: hist + binize ----
    __shared__ int sh[NREP][NUM_BINS];
    __shared__ int s_flag;

    for (int i = t; i < NREP * NUM_BINS; i += blockDim.x) ((int*)sh)[i] = 0;
    __syncthreads();

    const float4* p = (const float4*)(img + (size_t)c * npx);
    uchar4*       b = (uchar4*)(g_bins + (size_t)c * npx);
    const int sub = t & (NREP - 1);

    int i = blockIdx.x * blockDim.x + t;
    for (; i + stride < n4; i += 2 * stride) {
        float4 v0 = __ldcs(&p[i]);
        float4 v1 = __ldcs(&p[i + stride]);
        int b0 = min(NUM_BINS - 1, max(0, (int)v0.x));
        int b1 = min(NUM_BINS - 1, max(0, (int)v0.y));
        int b2 = min(NUM_BINS - 1, max(0, (int)v0.z));
        int b3 = min(NUM_BINS - 1, max(0, (int)v0.w));
        int b4 = min(NUM_BINS - 1, max(0, (int)v1.x));
        int b5 = min(NUM_BINS - 1, max(0, (int)v1.y));
        int b6 = min(NUM_BINS - 1, max(0, (int)v1.z));
        int b7 = min(NUM_BINS - 1, max(0, (int)v1.w));
        b[i] = make_uchar4((unsigned char)b0, (unsigned char)b1,
                           (unsigned char)b2, (unsigned char)b3);
        b[i + stride] = make_uchar4((unsigned char)b4, (unsigned char)b5,
                                    (unsigned char)b6, (unsigned char)b7);
        atomicAdd(&sh[sub][b0], 1);
        atomicAdd(&sh[sub][b1], 1);
        atomicAdd(&sh[sub][b2], 1);
        atomicAdd(&sh[sub][b3], 1);
        atomicAdd(&sh[sub][b4], 1);
        atomicAdd(&sh[sub][b5], 1);
        atomicAdd(&sh[sub][b6], 1);
        atomicAdd(&sh[sub][b7], 1);
    }
    if (i < n4) {
        float4 v = __ldcs(&p[i]);
        int b0 = min(NUM_BINS - 1, max(0, (int)v.x));
        int b1 = min(NUM_BINS - 1, max(0, (int)v.y));
        int b2 = min(NUM_BINS - 1, max(0, (int)v.z));
        int b3 = min(NUM_BINS - 1, max(0, (int)v.w));
        b[i] = make_uchar4((unsigned char)b0, (unsigned char)b1,
                           (unsigned char)b2, (unsigned char)b3);
        atomicAdd(&sh[sub][b0], 1);
        atomicAdd(&sh[sub][b1], 1);
        atomicAdd(&sh[sub][b2], 1);
        atomicAdd(&sh[sub][b3], 1);
    }
    __syncthreads();

    // flush: 256 bins, sum NREP replicas
    {
        int bin = t;
        int s = 0;
        #pragma unroll
        for (int r = 0; r < NREP; r++) s += sh[r][bin];
        if (s) atomicAdd(&g_hist[c][bin], s);
    }

    // ---- last arriving hist block computes the LUTs ----
    __threadfence();
    if (t == 0) {
        int done = atomicAdd(&g_ticket, 1);
        s_flag = (done == (int)(gridDim.x * NCH_SAMPLE) - 1);
    }
    __syncthreads();
    if (!s_flag) return;

    __shared__ int hist[NUM_BINS];
    __shared__ int cum[NUM_BINS];
    __shared__ int s_lastnz;

    for (int ch = 0; ch < NCH_SAMPLE; ch++) {
        int h = *(volatile int*)&g_hist[ch][t];
        hist[t] = h;
        cum[t] = h;
        if (t == 0) s_lastnz = 0;
        __syncthreads();

        #pragma unroll
        for (int off = 1; off < NUM_BINS; off <<= 1) {
            int tmp = (t >= off) ? cum[t - off] : 0;
            __syncthreads();
            cum[t] += tmp;
            __syncthreads();
        }
        if (h > 0) atomicMax(&s_lastnz, t);
        __syncthreads();

        const int total = cum[NUM_BINS - 1];
        const int step  = (total - hist[s_lastnz]) / (NUM_BINS - 1);

        float outv;
        if (step == 0) {
            outv = (float)t;                  // identity when step==0
        } else {
            int l = (t == 0) ? 0 : (cum[t - 1] + (step >> 1)) / step;
            outv = (float)min(NUM_BINS - 1, max(0, l));
        }
        g_lut[ch][t] = outv;
        g_hist[ch][t] = 0;                    // reset for next graph replay
        __syncthreads();
    }
    if (t == 0) g_ticket = 0;
}

// K2: sample channels only. 1 coalesced uchar4 load (L2-hot) -> 4 smem LUT
// gathers -> 1 coalesced float4 streaming store.
__global__ void __launch_bounds__(256)
apply_samples_kernel(float* __restrict__ out, int npx) {
    const int c = blockIdx.y;
    __shared__ float lut[NUM_BINS];
    for (int i = threadIdx.x; i < NUM_BINS; i += blockDim.x)
        lut[i] = g_lut[c][i];
    __syncthreads();

    const uchar4* b = (const uchar4*)(g_bins + (size_t)c * npx);
    float4*       q = (float4*)(out + (size_t)c * npx);
    const int n4 = npx >> 2;
    const int stride = gridDim.x * blockDim.x;

    int i = blockIdx.x * blockDim.x + threadIdx.x;
    for (; i + stride < n4; i += 2 * stride) {
        uchar4 v0 = __ldcg(&b[i]);
        uchar4 v1 = __ldcg(&b[i + stride]);
        float4 r0, r1;
        r0.x = lut[v0.x]; r0.y = lut[v0.y]; r0.z = lut[v0.z]; r0.w = lut[v0.w];
        r1.x = lut[v1.x]; r1.y = lut[v1.y]; r1.z = lut[v1.z]; r1.w = lut[v1.w];
        __stcs(&q[i], r0);
        __stcs(&q[i + stride], r1);
    }
    if (i < n4) {
        uchar4 v = __ldcg(&b[i]);
        float4 r;
        r.x = lut[v.x]; r.y = lut[v.y]; r.z = lut[v.z]; r.w = lut[v.w];
        __stcs(&q[i], r);
    }
}

extern "C" void kernel_launch(void* const* d_in, const int* in_sizes, int n_in,
                              void* d_out, int out_size) {
    const float* img = (const float*)d_in[0];
    float* out = (float*)d_out;
    const int npx = in_sizes[0] / NCH_TOTAL;   // 2048*4096

    hist_copy_kernel<<<dim3(384, NCH_TOTAL), 256>>>(img, out, npx);
    apply_samples_kernel<<<dim3(1024, NCH_SAMPLE), 256>>>(out, npx);
}